// round 1
// baseline (speedup 1.0000x reference)
#include <cuda_runtime.h>
#include <math.h>

#define B_   2
#define S_   2048
#define DM_  1024
#define H_   16
#define DH_  64
#define BSN_ (B_ * S_)     // 4096 rows
#define HB_  (H_ * B_)     // 32 (head,batch) pairs

// Scratch: [H][B][S][DH] contiguous. att's flat layout == the x matrix fed to Wo.
__device__ float g_q[HB_ * S_ * DH_];
__device__ float g_k[HB_ * S_ * DH_];
__device__ float g_v[HB_ * S_ * DH_];
__device__ float g_att[HB_ * S_ * DH_];

// ---------------------------------------------------------------------------
// Projection GEMM: C[4096, 1024] = X[4096,1024] @ W_blocked + bias
// W layout: [H, DM, DH]  -> column n maps to W[(n>>6)*DM*DH + d*DH + (n&63)]
// Output scatter: out[(n>>6)*(B*S*DH) + m*DH + (n&63)]  == [H,B,S,DH]
// ---------------------------------------------------------------------------
__global__ __launch_bounds__(256) void proj_gemm(
    const float* __restrict__ X, const float* __restrict__ W,
    const float* __restrict__ bias, float* __restrict__ out)
{
    __shared__ float As[8][128];   // A transposed: As[k][m]
    __shared__ float Bs[8][128];
    const int tid = threadIdx.x;
    const int m0 = blockIdx.y * 128;
    const int n0 = blockIdx.x * 128;
    const int tx = tid & 15, ty = tid >> 4;
    const int a_row = tid >> 1, a_col = (tid & 1) << 2;
    const int b_row = tid >> 5, b_col = (tid & 31) << 2;
    const int nb = n0 + b_col;
    const float* wptr = W + (nb >> 6) * (DM_ * DH_) + (nb & 63);

    float acc[8][8];
#pragma unroll
    for (int i = 0; i < 8; i++)
#pragma unroll
        for (int j = 0; j < 8; j++) acc[i][j] = 0.f;

    for (int k0 = 0; k0 < DM_; k0 += 8) {
        float4 av = *(const float4*)&X[(m0 + a_row) * DM_ + k0 + a_col];
        As[a_col + 0][a_row] = av.x;
        As[a_col + 1][a_row] = av.y;
        As[a_col + 2][a_row] = av.z;
        As[a_col + 3][a_row] = av.w;
        *(float4*)&Bs[b_row][b_col] = *(const float4*)&wptr[(size_t)(k0 + b_row) * DH_];
        __syncthreads();
#pragma unroll
        for (int kk = 0; kk < 8; kk++) {
            float a[8], b[8];
            *(float4*)&a[0] = *(float4*)&As[kk][ty * 8];
            *(float4*)&a[4] = *(float4*)&As[kk][ty * 8 + 4];
            *(float4*)&b[0] = *(float4*)&Bs[kk][tx * 8];
            *(float4*)&b[4] = *(float4*)&Bs[kk][tx * 8 + 4];
#pragma unroll
            for (int i = 0; i < 8; i++)
#pragma unroll
                for (int j = 0; j < 8; j++)
                    acc[i][j] = fmaf(a[i], b[j], acc[i][j]);
        }
        __syncthreads();
    }
#pragma unroll
    for (int i = 0; i < 8; i++) {
        const int m = m0 + ty * 8 + i;
#pragma unroll
        for (int j = 0; j < 8; j++) {
            const int n = n0 + tx * 8 + j;
            out[(size_t)(n >> 6) * (B_ * S_ * DH_) + (size_t)m * DH_ + (n & 63)] =
                acc[i][j] + bias[n];
        }
    }
}

// ---------------------------------------------------------------------------
// Output GEMM: out[4096, 1024] = Xatt[4096,1024] @ Wo[1024,1024] + bo
// ---------------------------------------------------------------------------
__global__ __launch_bounds__(256) void out_gemm(
    const float* __restrict__ X, const float* __restrict__ Wo,
    const float* __restrict__ bo, float* __restrict__ out)
{
    __shared__ float As[8][128];
    __shared__ float Bs[8][128];
    const int tid = threadIdx.x;
    const int m0 = blockIdx.y * 128;
    const int n0 = blockIdx.x * 128;
    const int tx = tid & 15, ty = tid >> 4;
    const int a_row = tid >> 1, a_col = (tid & 1) << 2;
    const int b_row = tid >> 5, b_col = (tid & 31) << 2;

    float acc[8][8];
#pragma unroll
    for (int i = 0; i < 8; i++)
#pragma unroll
        for (int j = 0; j < 8; j++) acc[i][j] = 0.f;

    for (int k0 = 0; k0 < DM_; k0 += 8) {
        float4 av = *(const float4*)&X[(m0 + a_row) * DM_ + k0 + a_col];
        As[a_col + 0][a_row] = av.x;
        As[a_col + 1][a_row] = av.y;
        As[a_col + 2][a_row] = av.z;
        As[a_col + 3][a_row] = av.w;
        *(float4*)&Bs[b_row][b_col] =
            *(const float4*)&Wo[(size_t)(k0 + b_row) * DM_ + n0 + b_col];
        __syncthreads();
#pragma unroll
        for (int kk = 0; kk < 8; kk++) {
            float a[8], b[8];
            *(float4*)&a[0] = *(float4*)&As[kk][ty * 8];
            *(float4*)&a[4] = *(float4*)&As[kk][ty * 8 + 4];
            *(float4*)&b[0] = *(float4*)&Bs[kk][tx * 8];
            *(float4*)&b[4] = *(float4*)&Bs[kk][tx * 8 + 4];
#pragma unroll
            for (int i = 0; i < 8; i++)
#pragma unroll
                for (int j = 0; j < 8; j++)
                    acc[i][j] = fmaf(a[i], b[j], acc[i][j]);
        }
        __syncthreads();
    }
#pragma unroll
    for (int i = 0; i < 8; i++) {
        const int m = m0 + ty * 8 + i;
#pragma unroll
        for (int j = 0; j < 8; j++) {
            const int n = n0 + tx * 8 + j;
            out[(size_t)m * DM_ + n] = acc[i][j] + bo[n];
        }
    }
}

// ---------------------------------------------------------------------------
// Flash attention (fp32): one block = 64 query rows of one (h,b).
// Online softmax; K tile stored transposed [d][j] (pitch 68), P overlays K.
// ---------------------------------------------------------------------------
#define QP_ 64
#define KPP_ 68
#define VP_ 64
#define ATTN_SMEM ((64 * QP_ + 64 * KPP_ + 64 * VP_) * 4)  // 50176 bytes

__global__ __launch_bounds__(256) void attn_kernel(
    const float* __restrict__ Q, const float* __restrict__ K,
    const float* __restrict__ V, float* __restrict__ O)
{
    extern __shared__ float sm[];
    float* Qs  = sm;                    // [64][64]
    float* KPs = sm + 64 * QP_;         // K^T [64 d][68] then P [64 i][68]
    float* Vs  = KPs + 64 * KPP_;       // [64][64]

    const int tid = threadIdx.x;
    const int tx = tid & 15, ty = tid >> 4;
    const int hb = blockIdx.y;
    const int q0 = blockIdx.x * 64;
    const float* Qp = Q + (size_t)hb * (S_ * DH_);
    const float* Kp = K + (size_t)hb * (S_ * DH_);
    const float* Vp = V + (size_t)hb * (S_ * DH_);

#pragma unroll
    for (int i = tid; i < 64 * 16; i += 256) {
        const int r = i >> 4, c = (i & 15) << 2;
        *(float4*)&Qs[r * QP_ + c] = *(const float4*)&Qp[(size_t)(q0 + r) * DH_ + c];
    }

    float m_i[4], l_i[4], accO[4][4];
#pragma unroll
    for (int r = 0; r < 4; r++) {
        m_i[r] = -1e30f; l_i[r] = 0.f;
#pragma unroll
        for (int c = 0; c < 4; c++) accO[r][c] = 0.f;
    }

    for (int kt = 0; kt < S_; kt += 64) {
        __syncthreads();   // previous iter done reading KPs(P)/Vs
#pragma unroll
        for (int i = tid; i < 64 * 16; i += 256) {
            const int r = i >> 4, c = (i & 15) << 2;
            float4 kv = *(const float4*)&Kp[(size_t)(kt + r) * DH_ + c];
            KPs[(c + 0) * KPP_ + r] = kv.x;
            KPs[(c + 1) * KPP_ + r] = kv.y;
            KPs[(c + 2) * KPP_ + r] = kv.z;
            KPs[(c + 3) * KPP_ + r] = kv.w;
            *(float4*)&Vs[r * VP_ + c] = *(const float4*)&Vp[(size_t)(kt + r) * DH_ + c];
        }
        __syncthreads();

        // S = Q K^T   (4x4 per thread)
        float s[4][4];
#pragma unroll
        for (int r = 0; r < 4; r++)
#pragma unroll
            for (int c = 0; c < 4; c++) s[r][c] = 0.f;

#pragma unroll 8
        for (int d = 0; d < 64; d++) {
            float a[4];
            a[0] = Qs[(ty * 4 + 0) * QP_ + d];
            a[1] = Qs[(ty * 4 + 1) * QP_ + d];
            a[2] = Qs[(ty * 4 + 2) * QP_ + d];
            a[3] = Qs[(ty * 4 + 3) * QP_ + d];
            float4 b4 = *(const float4*)&KPs[d * KPP_ + tx * 4];
            float b[4] = {b4.x, b4.y, b4.z, b4.w};
#pragma unroll
            for (int r = 0; r < 4; r++)
#pragma unroll
                for (int c = 0; c < 4; c++)
                    s[r][c] = fmaf(a[r], b[c], s[r][c]);
        }

        // online softmax (rows shared by 16 lanes: contiguous in warp, xor<16 safe)
        float p[4][4];
#pragma unroll
        for (int r = 0; r < 4; r++) {
#pragma unroll
            for (int c = 0; c < 4; c++) s[r][c] *= 0.125f;   // 1/sqrt(64)
            float mx = fmaxf(fmaxf(s[r][0], s[r][1]), fmaxf(s[r][2], s[r][3]));
            mx = fmaxf(mx, __shfl_xor_sync(0xffffffffu, mx, 8));
            mx = fmaxf(mx, __shfl_xor_sync(0xffffffffu, mx, 4));
            mx = fmaxf(mx, __shfl_xor_sync(0xffffffffu, mx, 2));
            mx = fmaxf(mx, __shfl_xor_sync(0xffffffffu, mx, 1));
            const float mnew = fmaxf(m_i[r], mx);
            const float corr = __expf(m_i[r] - mnew);
            float rs = 0.f;
#pragma unroll
            for (int c = 0; c < 4; c++) {
                p[r][c] = __expf(s[r][c] - mnew);
                rs += p[r][c];
            }
            rs += __shfl_xor_sync(0xffffffffu, rs, 8);
            rs += __shfl_xor_sync(0xffffffffu, rs, 4);
            rs += __shfl_xor_sync(0xffffffffu, rs, 2);
            rs += __shfl_xor_sync(0xffffffffu, rs, 1);
            l_i[r] = l_i[r] * corr + rs;
            m_i[r] = mnew;
#pragma unroll
            for (int c = 0; c < 4; c++) accO[r][c] *= corr;
        }

        __syncthreads();   // everyone done reading K from KPs
#pragma unroll
        for (int r = 0; r < 4; r++)
#pragma unroll
            for (int c = 0; c < 4; c++)
                KPs[(ty * 4 + r) * KPP_ + tx * 4 + c] = p[r][c];
        __syncthreads();

        // O += P V
#pragma unroll 8
        for (int j = 0; j < 64; j++) {
            float a[4];
            a[0] = KPs[(ty * 4 + 0) * KPP_ + j];
            a[1] = KPs[(ty * 4 + 1) * KPP_ + j];
            a[2] = KPs[(ty * 4 + 2) * KPP_ + j];
            a[3] = KPs[(ty * 4 + 3) * KPP_ + j];
            float4 b4 = *(const float4*)&Vs[j * VP_ + tx * 4];
            float b[4] = {b4.x, b4.y, b4.z, b4.w};
#pragma unroll
            for (int r = 0; r < 4; r++)
#pragma unroll
                for (int c = 0; c < 4; c++)
                    accO[r][c] = fmaf(a[r], b[c], accO[r][c]);
        }
    }

#pragma unroll
    for (int r = 0; r < 4; r++) {
        const float inv = 1.f / l_i[r];
        const size_t row = (size_t)hb * S_ + q0 + ty * 4 + r;
#pragma unroll
        for (int c = 0; c < 4; c++)
            O[row * DH_ + tx * 4 + c] = accO[r][c] * inv;
    }
}

// ---------------------------------------------------------------------------
extern "C" void kernel_launch(void* const* d_in, const int* in_sizes, int n_in,
                              void* d_out, int out_size)
{
    const float* query = (const float*)d_in[0];
    const float* key_  = (const float*)d_in[1];
    const float* value = (const float*)d_in[2];
    const float* Wq    = (const float*)d_in[3];
    const float* bq    = (const float*)d_in[4];
    const float* Wk    = (const float*)d_in[5];
    const float* bk    = (const float*)d_in[6];
    const float* Wv    = (const float*)d_in[7];
    const float* bv    = (const float*)d_in[8];
    const float* Wo    = (const float*)d_in[9];
    const float* bo    = (const float*)d_in[10];
    float* out = (float*)d_out;

    float *qb, *kb, *vb, *ab;
    cudaGetSymbolAddress((void**)&qb, g_q);
    cudaGetSymbolAddress((void**)&kb, g_k);
    cudaGetSymbolAddress((void**)&vb, g_v);
    cudaGetSymbolAddress((void**)&ab, g_att);

    cudaFuncSetAttribute(attn_kernel,
                         cudaFuncAttributeMaxDynamicSharedMemorySize, ATTN_SMEM);

    const dim3 gGemm(DM_ / 128, BSN_ / 128);   // (8, 32)
    proj_gemm<<<gGemm, 256>>>(query, Wq, bq, qb);
    proj_gemm<<<gGemm, 256>>>(key_,  Wk, bk, kb);
    proj_gemm<<<gGemm, 256>>>(value, Wv, bv, vb);

    const dim3 gAttn(S_ / 64, HB_);            // (32, 32)
    attn_kernel<<<gAttn, 256, ATTN_SMEM>>>(qb, kb, vb, ab);

    out_gemm<<<gGemm, 256>>>(ab, Wo, bo, out);
}

// round 4
// speedup vs baseline: 1.3874x; 1.3874x over previous
#include <cuda_runtime.h>
#include <cstdint>
#include <math.h>

#define B_   2
#define S_   2048
#define DM_  1024
#define H_   16
#define DH_  64
#define BSN_ (B_ * S_)     // 4096 rows
#define HB_  (H_ * B_)     // 32 (head,batch) pairs

// Scratch: [H][B][S][DH] contiguous. att's flat layout == the x matrix fed to Wo.
__device__ float g_q[HB_ * S_ * DH_];
__device__ float g_k[HB_ * S_ * DH_];
__device__ float g_v[HB_ * S_ * DH_];
__device__ float g_att[HB_ * S_ * DH_];
// Repacked weights: [n][k] K-major, n = output column of the [1024x1024] GEMM
__device__ float g_wq[DM_ * DM_];
__device__ float g_wk[DM_ * DM_];
__device__ float g_wv[DM_ * DM_];
__device__ float g_wo[DM_ * DM_];

// ---------------------------------------------------------------------------
// mma.sync tf32 helpers (sm_80+ features only — no sm_100a suffix needed)
// ---------------------------------------------------------------------------
__device__ __forceinline__ uint32_t to_tf32(float x) {
    uint32_t r;
    asm("cvt.rna.tf32.f32 %0, %1;" : "=r"(r) : "f"(x));
    return r;
}

// D(16x8) += A(16x8) * B(8x8), A row-major frag, B col-major frag
__device__ __forceinline__ void mma_16n8k8(float* c, const uint32_t* a, const uint32_t* b) {
    asm volatile(
        "mma.sync.aligned.m16n8k8.row.col.f32.tf32.tf32.f32 "
        "{%0,%1,%2,%3}, {%4,%5,%6,%7}, {%8,%9}, {%0,%1,%2,%3};\n"
        : "+f"(c[0]), "+f"(c[1]), "+f"(c[2]), "+f"(c[3])
        : "r"(a[0]), "r"(a[1]), "r"(a[2]), "r"(a[3]), "r"(b[0]), "r"(b[1]));
}

// ---------------------------------------------------------------------------
// Weight repack kernels
// ---------------------------------------------------------------------------
// W[H][DM][DH] -> WT[n][d], n = h*64 + j
__global__ __launch_bounds__(256) void repack_w(const float* __restrict__ W,
                                                float* __restrict__ WT)
{
    __shared__ float t[64][65];
    const int h = blockIdx.x;
    const int d0 = blockIdx.y * 64;
    const float* src = W + (size_t)h * DM_ * DH_;
    const int tid = threadIdx.x;
    for (int i = tid; i < 4096; i += 256) {
        int d = i >> 6, j = i & 63;
        t[d][j] = src[(size_t)(d0 + d) * DH_ + j];
    }
    __syncthreads();
    for (int i = tid; i < 4096; i += 256) {
        int j = i >> 6, d = i & 63;
        WT[(size_t)(h * 64 + j) * DM_ + d0 + d] = t[d][j];
    }
}

// Wo[k][n] -> WT[n][k]
__global__ __launch_bounds__(256) void transpose_wo(const float* __restrict__ Wo,
                                                    float* __restrict__ WT)
{
    __shared__ float t[64][65];
    const int k0 = blockIdx.x * 64;
    const int n0 = blockIdx.y * 64;
    const int tid = threadIdx.x;
    for (int i = tid; i < 4096; i += 256) {
        int k = i >> 6, n = i & 63;
        t[k][n] = Wo[(size_t)(k0 + k) * DM_ + n0 + n];
    }
    __syncthreads();
    for (int i = tid; i < 4096; i += 256) {
        int n = i >> 6, k = i & 63;
        WT[(size_t)(n0 + n) * DM_ + k0 + k] = t[k][n];
    }
}

// ---------------------------------------------------------------------------
// tf32 mma.sync GEMM: C[4096,1024] = A[4096,1024] @ Bm^T (Bm stored [n][k]) + bias
// CTA tile 128x128, 256 threads = 8 warps (2m x 4n), warp tile 64x32.
// K chunks of 32, double-buffered smem with register prefetch.
//
// SMEM per stage:
//   A: fragment-packed. frag(kt 0..3, mtg 0..7, lane) = 16B {a0,a1,a2,a3}
//      at offset ((kt*8 + mtg)*32 + lane)*16.  Size 16384 B.
//      a0=(R,C) a1=(R+8,C) a2=(R,C+4) a3=(R+8,C+4), R=mtg*16+(lane>>2),
//      C=kt*8+(lane&3)  [PTX m16n8k8 A-fragment layout]
//   B: row-major [128][36] floats (pad 36 -> fragment lds.32 conflict-free).
//      Size 18432 B.
// scatter=1: out[(n>>6)*(BSN*64) + m*64 + (n&63)]  (== [H,B,S,64])
// scatter=0: out[m*1024 + n]
// ---------------------------------------------------------------------------
#define ASZ 16384
#define BSZ 18432
#define STG (ASZ + BSZ)        // 34816
#define GEMM_SMEM (2 * STG)    // 69632

__global__ __launch_bounds__(256) void gemm_mma(
    const float* __restrict__ A, const float* __restrict__ Bm,
    const float* __restrict__ bias, float* __restrict__ out, int scatter)
{
    extern __shared__ __align__(16) char smraw[];
    const int tid = threadIdx.x, lane = tid & 31, wid = tid >> 5;
    const int wm = wid & 1, wn = wid >> 1;          // warp grid 2(m) x 4(n)
    const int m0 = blockIdx.y * 128, n0 = blockIdx.x * 128;

    float acc[4][4][4];
#pragma unroll
    for (int i = 0; i < 4; i++)
#pragma unroll
        for (int j = 0; j < 4; j++)
#pragma unroll
            for (int k = 0; k < 4; k++) acc[i][j][k] = 0.f;

    // ---- per-thread loader geometry ----
    // A: this thread owns frags (kt=f, mtg=wid, lane) for f=0..3
    const int aR = wid * 16 + (lane >> 2);          // gmem row within tile
    const int aC = lane & 3;                        // col offset within ktile
    // B: element float4s: idx = tid + f*256 -> n=(tid>>3)+f*32, c4=tid&7
    const int bN = tid >> 3;
    const int bC4 = tid & 7;

    float pa[4][4];     // prefetch A frags [f][reg]
    float4 pb[4];       // prefetch B float4s

    // ---------------- LDG chunk macro ----------------
#define LDG_CHUNK(c) do {                                                     \
    const int k0_ = (c) * 32;                                                 \
    const float* ar0 = A + (size_t)(m0 + aR) * DM_ + k0_ + aC;                \
    const float* ar8 = ar0 + 8 * DM_;                                         \
    _Pragma("unroll")                                                         \
    for (int f = 0; f < 4; f++) {                                             \
        pa[f][0] = ar0[f * 8];                                                \
        pa[f][1] = ar8[f * 8];                                                \
        pa[f][2] = ar0[f * 8 + 4];                                            \
        pa[f][3] = ar8[f * 8 + 4];                                            \
    }                                                                         \
    _Pragma("unroll")                                                         \
    for (int f = 0; f < 4; f++)                                               \
        pb[f] = *(const float4*)&Bm[(size_t)(n0 + bN + f * 32) * DM_ + k0_ + bC4 * 4]; \
} while (0)

    // ---------------- STS chunk macro ----------------
#define STS_CHUNK(s) do {                                                     \
    char* stg = smraw + (s) * STG;                                            \
    _Pragma("unroll")                                                         \
    for (int f = 0; f < 4; f++) {                                             \
        uint4 v;                                                              \
        v.x = to_tf32(pa[f][0]); v.y = to_tf32(pa[f][1]);                     \
        v.z = to_tf32(pa[f][2]); v.w = to_tf32(pa[f][3]);                     \
        *(uint4*)(stg + (size_t)(tid + f * 256) * 16) = v;                    \
    }                                                                         \
    uint32_t* bs = (uint32_t*)(stg + ASZ);                                    \
    _Pragma("unroll")                                                         \
    for (int f = 0; f < 4; f++) {                                             \
        uint32_t* d = bs + (bN + f * 32) * 36 + bC4 * 4;                      \
        d[0] = to_tf32(pb[f].x); d[1] = to_tf32(pb[f].y);                     \
        d[2] = to_tf32(pb[f].z); d[3] = to_tf32(pb[f].w);                     \
    }                                                                         \
} while (0)

    // ---------------- compute chunk macro ----------------
#define MMA_CHUNK(s) do {                                                     \
    char* stg = smraw + (s) * STG;                                            \
    const uint32_t* bs = (const uint32_t*)(stg + ASZ);                        \
    _Pragma("unroll")                                                         \
    for (int kt = 0; kt < 4; kt++) {                                          \
        uint32_t af[4][4];                                                    \
        _Pragma("unroll")                                                     \
        for (int mt = 0; mt < 4; mt++) {                                      \
            uint4 v = *(const uint4*)(stg +                                   \
                (size_t)(((kt * 8) + (wm * 4 + mt)) * 32 + lane) * 16);       \
            af[mt][0] = v.x; af[mt][1] = v.y; af[mt][2] = v.z; af[mt][3] = v.w; \
        }                                                                     \
        uint32_t bf[4][2];                                                    \
        _Pragma("unroll")                                                     \
        for (int nt = 0; nt < 4; nt++) {                                      \
            const uint32_t* bp = bs +                                         \
                ((wn * 4 + nt) * 8 + (lane >> 2)) * 36 + kt * 8 + (lane & 3); \
            bf[nt][0] = bp[0];                                                \
            bf[nt][1] = bp[4];                                                \
        }                                                                     \
        _Pragma("unroll")                                                     \
        for (int mt = 0; mt < 4; mt++)                                        \
            _Pragma("unroll")                                                 \
            for (int nt = 0; nt < 4; nt++)                                    \
                mma_16n8k8(acc[mt][nt], af[mt], bf[nt]);                      \
    }                                                                         \
} while (0)

    // prologue
    LDG_CHUNK(0);
    STS_CHUNK(0);
    __syncthreads();

    for (int c = 0; c < 32; c++) {
        if (c < 31) LDG_CHUNK(c + 1);
        MMA_CHUNK(c & 1);
        if (c < 31) {
            STS_CHUNK((c + 1) & 1);
            __syncthreads();
        }
    }

    // epilogue: C layout c0=(r,2q) c1=(r,2q+1) c2=(r+8,2q) c3=(r+8,2q+1)
#pragma unroll
    for (int mt = 0; mt < 4; mt++) {
#pragma unroll
        for (int nt = 0; nt < 4; nt++) {
            const int m = m0 + wm * 64 + mt * 16 + (lane >> 2);
            const int n = n0 + wn * 32 + nt * 8 + 2 * (lane & 3);
            float2 v01, v23;
            v01.x = acc[mt][nt][0] + bias[n];
            v01.y = acc[mt][nt][1] + bias[n + 1];
            v23.x = acc[mt][nt][2] + bias[n];
            v23.y = acc[mt][nt][3] + bias[n + 1];
            if (scatter) {
                const size_t base = (size_t)(n >> 6) * ((size_t)BSN_ * DH_) + (n & 63);
                *(float2*)&out[base + (size_t)m * DH_] = v01;
                *(float2*)&out[base + (size_t)(m + 8) * DH_] = v23;
            } else {
                *(float2*)&out[(size_t)m * DM_ + n] = v01;
                *(float2*)&out[(size_t)(m + 8) * DM_ + n] = v23;
            }
        }
    }
#undef LDG_CHUNK
#undef STS_CHUNK
#undef MMA_CHUNK
}

// ---------------------------------------------------------------------------
// Flash attention (fp32): unchanged from the passing R1 version.
// ---------------------------------------------------------------------------
#define QP_ 64
#define KPP_ 68
#define VP_ 64
#define ATTN_SMEM ((64 * QP_ + 64 * KPP_ + 64 * VP_) * 4)  // 50176 bytes

__global__ __launch_bounds__(256) void attn_kernel(
    const float* __restrict__ Q, const float* __restrict__ K,
    const float* __restrict__ V, float* __restrict__ O)
{
    extern __shared__ __align__(16) float smf[];
    float* Qs  = smf;
    float* KPs = smf + 64 * QP_;
    float* Vs  = KPs + 64 * KPP_;

    const int tid = threadIdx.x;
    const int tx = tid & 15, ty = tid >> 4;
    const int hb = blockIdx.y;
    const int q0 = blockIdx.x * 64;
    const float* Qp = Q + (size_t)hb * (S_ * DH_);
    const float* Kp = K + (size_t)hb * (S_ * DH_);
    const float* Vp = V + (size_t)hb * (S_ * DH_);

#pragma unroll
    for (int i = tid; i < 64 * 16; i += 256) {
        const int r = i >> 4, c = (i & 15) << 2;
        *(float4*)&Qs[r * QP_ + c] = *(const float4*)&Qp[(size_t)(q0 + r) * DH_ + c];
    }

    float m_i[4], l_i[4], accO[4][4];
#pragma unroll
    for (int r = 0; r < 4; r++) {
        m_i[r] = -1e30f; l_i[r] = 0.f;
#pragma unroll
        for (int c = 0; c < 4; c++) accO[r][c] = 0.f;
    }

    for (int kt = 0; kt < S_; kt += 64) {
        __syncthreads();
#pragma unroll
        for (int i = tid; i < 64 * 16; i += 256) {
            const int r = i >> 4, c = (i & 15) << 2;
            float4 kv = *(const float4*)&Kp[(size_t)(kt + r) * DH_ + c];
            KPs[(c + 0) * KPP_ + r] = kv.x;
            KPs[(c + 1) * KPP_ + r] = kv.y;
            KPs[(c + 2) * KPP_ + r] = kv.z;
            KPs[(c + 3) * KPP_ + r] = kv.w;
            *(float4*)&Vs[r * VP_ + c] = *(const float4*)&Vp[(size_t)(kt + r) * DH_ + c];
        }
        __syncthreads();

        float s[4][4];
#pragma unroll
        for (int r = 0; r < 4; r++)
#pragma unroll
            for (int c = 0; c < 4; c++) s[r][c] = 0.f;

#pragma unroll 8
        for (int d = 0; d < 64; d++) {
            float a[4];
            a[0] = Qs[(ty * 4 + 0) * QP_ + d];
            a[1] = Qs[(ty * 4 + 1) * QP_ + d];
            a[2] = Qs[(ty * 4 + 2) * QP_ + d];
            a[3] = Qs[(ty * 4 + 3) * QP_ + d];
            float4 b4 = *(const float4*)&KPs[d * KPP_ + tx * 4];
            float b[4] = {b4.x, b4.y, b4.z, b4.w};
#pragma unroll
            for (int r = 0; r < 4; r++)
#pragma unroll
                for (int c = 0; c < 4; c++)
                    s[r][c] = fmaf(a[r], b[c], s[r][c]);
        }

        float p[4][4];
#pragma unroll
        for (int r = 0; r < 4; r++) {
#pragma unroll
            for (int c = 0; c < 4; c++) s[r][c] *= 0.125f;
            float mx = fmaxf(fmaxf(s[r][0], s[r][1]), fmaxf(s[r][2], s[r][3]));
            mx = fmaxf(mx, __shfl_xor_sync(0xffffffffu, mx, 8));
            mx = fmaxf(mx, __shfl_xor_sync(0xffffffffu, mx, 4));
            mx = fmaxf(mx, __shfl_xor_sync(0xffffffffu, mx, 2));
            mx = fmaxf(mx, __shfl_xor_sync(0xffffffffu, mx, 1));
            const float mnew = fmaxf(m_i[r], mx);
            const float corr = __expf(m_i[r] - mnew);
            float rs = 0.f;
#pragma unroll
            for (int c = 0; c < 4; c++) {
                p[r][c] = __expf(s[r][c] - mnew);
                rs += p[r][c];
            }
            rs += __shfl_xor_sync(0xffffffffu, rs, 8);
            rs += __shfl_xor_sync(0xffffffffu, rs, 4);
            rs += __shfl_xor_sync(0xffffffffu, rs, 2);
            rs += __shfl_xor_sync(0xffffffffu, rs, 1);
            l_i[r] = l_i[r] * corr + rs;
            m_i[r] = mnew;
#pragma unroll
            for (int c = 0; c < 4; c++) accO[r][c] *= corr;
        }

        __syncthreads();
#pragma unroll
        for (int r = 0; r < 4; r++)
#pragma unroll
            for (int c = 0; c < 4; c++)
                KPs[(ty * 4 + r) * KPP_ + tx * 4 + c] = p[r][c];
        __syncthreads();

#pragma unroll 8
        for (int j = 0; j < 64; j++) {
            float a[4];
            a[0] = KPs[(ty * 4 + 0) * KPP_ + j];
            a[1] = KPs[(ty * 4 + 1) * KPP_ + j];
            a[2] = KPs[(ty * 4 + 2) * KPP_ + j];
            a[3] = KPs[(ty * 4 + 3) * KPP_ + j];
            float4 b4 = *(const float4*)&Vs[j * VP_ + tx * 4];
            float b[4] = {b4.x, b4.y, b4.z, b4.w};
#pragma unroll
            for (int r = 0; r < 4; r++)
#pragma unroll
                for (int c = 0; c < 4; c++)
                    accO[r][c] = fmaf(a[r], b[c], accO[r][c]);
        }
    }

#pragma unroll
    for (int r = 0; r < 4; r++) {
        const float inv = 1.f / l_i[r];
        const size_t row = (size_t)hb * S_ + q0 + ty * 4 + r;
#pragma unroll
        for (int c = 0; c < 4; c++)
            O[row * DH_ + tx * 4 + c] = accO[r][c] * inv;
    }
}

// ---------------------------------------------------------------------------
extern "C" void kernel_launch(void* const* d_in, const int* in_sizes, int n_in,
                              void* d_out, int out_size)
{
    const float* query = (const float*)d_in[0];
    const float* key_  = (const float*)d_in[1];
    const float* value = (const float*)d_in[2];
    const float* Wq    = (const float*)d_in[3];
    const float* bq    = (const float*)d_in[4];
    const float* Wk    = (const float*)d_in[5];
    const float* bk    = (const float*)d_in[6];
    const float* Wv    = (const float*)d_in[7];
    const float* bv    = (const float*)d_in[8];
    const float* Wo    = (const float*)d_in[9];
    const float* bo    = (const float*)d_in[10];
    float* out = (float*)d_out;

    float *qb, *kb, *vb, *ab, *wq, *wk, *wv, *wo;
    cudaGetSymbolAddress((void**)&qb, g_q);
    cudaGetSymbolAddress((void**)&kb, g_k);
    cudaGetSymbolAddress((void**)&vb, g_v);
    cudaGetSymbolAddress((void**)&ab, g_att);
    cudaGetSymbolAddress((void**)&wq, g_wq);
    cudaGetSymbolAddress((void**)&wk, g_wk);
    cudaGetSymbolAddress((void**)&wv, g_wv);
    cudaGetSymbolAddress((void**)&wo, g_wo);

    cudaFuncSetAttribute(gemm_mma, cudaFuncAttributeMaxDynamicSharedMemorySize, GEMM_SMEM);
    cudaFuncSetAttribute(attn_kernel, cudaFuncAttributeMaxDynamicSharedMemorySize, ATTN_SMEM);

    // Repack weights into plain K-major [n][k] matrices
    repack_w<<<dim3(16, 16), 256>>>(Wq, wq);
    repack_w<<<dim3(16, 16), 256>>>(Wk, wk);
    repack_w<<<dim3(16, 16), 256>>>(Wv, wv);
    transpose_wo<<<dim3(16, 16), 256>>>(Wo, wo);

    const dim3 gGemm(DM_ / 128, BSN_ / 128);   // (8, 32)
    gemm_mma<<<gGemm, 256, GEMM_SMEM>>>(query, wq, bq, qb, 1);
    gemm_mma<<<gGemm, 256, GEMM_SMEM>>>(key_,  wk, bk, kb, 1);
    gemm_mma<<<gGemm, 256, GEMM_SMEM>>>(value, wv, bv, vb, 1);

    const dim3 gAttn(S_ / 64, HB_);            // (32, 32)
    attn_kernel<<<gAttn, 256, ATTN_SMEM>>>(qb, kb, vb, ab);

    gemm_mma<<<gGemm, 256, GEMM_SMEM>>>(ab, wo, bo, out, 0);
}

// round 5
// speedup vs baseline: 2.5400x; 1.8307x over previous
#include <cuda_runtime.h>
#include <cstdint>
#include <math.h>

#define B_   2
#define S_   2048
#define DM_  1024
#define H_   16
#define DH_  64
#define BSN_ (B_ * S_)     // 4096 rows
#define HB_  (H_ * B_)     // 32 (head,batch) pairs

// Scratch: [H][B][S][DH] contiguous. att's flat layout == the x matrix fed to Wo.
__device__ float g_q[HB_ * S_ * DH_];
__device__ float g_k[HB_ * S_ * DH_];
__device__ float g_v[HB_ * S_ * DH_];
__device__ float g_att[HB_ * S_ * DH_];
// Repacked weights: [n][k] K-major, n = output column of the [1024x1024] GEMM
__device__ float g_wq[DM_ * DM_];
__device__ float g_wk[DM_ * DM_];
__device__ float g_wv[DM_ * DM_];
__device__ float g_wo[DM_ * DM_];

// ---------------------------------------------------------------------------
// mma.sync tf32 helpers
// ---------------------------------------------------------------------------
__device__ __forceinline__ uint32_t to_tf32(float x) {
    uint32_t r;
    asm("cvt.rna.tf32.f32 %0, %1;" : "=r"(r) : "f"(x));
    return r;
}

// D(16x8) += A(16x8) * B(8x8), A row-major frag, B col-major frag
__device__ __forceinline__ void mma_16n8k8(float* c, const uint32_t* a, const uint32_t* b) {
    asm volatile(
        "mma.sync.aligned.m16n8k8.row.col.f32.tf32.tf32.f32 "
        "{%0,%1,%2,%3}, {%4,%5,%6,%7}, {%8,%9}, {%0,%1,%2,%3};\n"
        : "+f"(c[0]), "+f"(c[1]), "+f"(c[2]), "+f"(c[3])
        : "r"(a[0]), "r"(a[1]), "r"(a[2]), "r"(a[3]), "r"(b[0]), "r"(b[1]));
}

// ---------------------------------------------------------------------------
// Weight repack kernels
// ---------------------------------------------------------------------------
__global__ __launch_bounds__(256) void repack_w(const float* __restrict__ W,
                                                float* __restrict__ WT)
{
    __shared__ float t[64][65];
    const int h = blockIdx.x;
    const int d0 = blockIdx.y * 64;
    const float* src = W + (size_t)h * DM_ * DH_;
    const int tid = threadIdx.x;
    for (int i = tid; i < 4096; i += 256) {
        int d = i >> 6, j = i & 63;
        t[d][j] = src[(size_t)(d0 + d) * DH_ + j];
    }
    __syncthreads();
    for (int i = tid; i < 4096; i += 256) {
        int j = i >> 6, d = i & 63;
        WT[(size_t)(h * 64 + j) * DM_ + d0 + d] = t[d][j];
    }
}

__global__ __launch_bounds__(256) void transpose_wo(const float* __restrict__ Wo,
                                                    float* __restrict__ WT)
{
    __shared__ float t[64][65];
    const int k0 = blockIdx.x * 64;
    const int n0 = blockIdx.y * 64;
    const int tid = threadIdx.x;
    for (int i = tid; i < 4096; i += 256) {
        int k = i >> 6, n = i & 63;
        t[k][n] = Wo[(size_t)(k0 + k) * DM_ + n0 + n];
    }
    __syncthreads();
    for (int i = tid; i < 4096; i += 256) {
        int n = i >> 6, k = i & 63;
        WT[(size_t)(n0 + n) * DM_ + k0 + k] = t[k][n];
    }
}

// ---------------------------------------------------------------------------
// tf32 mma.sync GEMM (unchanged from R4, passing)
// ---------------------------------------------------------------------------
#define ASZ 16384
#define BSZ 18432
#define STG (ASZ + BSZ)        // 34816
#define GEMM_SMEM (2 * STG)    // 69632

__global__ __launch_bounds__(256) void gemm_mma(
    const float* __restrict__ A, const float* __restrict__ Bm,
    const float* __restrict__ bias, float* __restrict__ out, int scatter)
{
    extern __shared__ __align__(16) char smraw[];
    const int tid = threadIdx.x, lane = tid & 31, wid = tid >> 5;
    const int wm = wid & 1, wn = wid >> 1;
    const int m0 = blockIdx.y * 128, n0 = blockIdx.x * 128;

    float acc[4][4][4];
#pragma unroll
    for (int i = 0; i < 4; i++)
#pragma unroll
        for (int j = 0; j < 4; j++)
#pragma unroll
            for (int k = 0; k < 4; k++) acc[i][j][k] = 0.f;

    const int aR = wid * 16 + (lane >> 2);
    const int aC = lane & 3;
    const int bN = tid >> 3;
    const int bC4 = tid & 7;

    float pa[4][4];
    float4 pb[4];

#define LDG_CHUNK(c) do {                                                     \
    const int k0_ = (c) * 32;                                                 \
    const float* ar0 = A + (size_t)(m0 + aR) * DM_ + k0_ + aC;                \
    const float* ar8 = ar0 + 8 * DM_;                                         \
    _Pragma("unroll")                                                         \
    for (int f = 0; f < 4; f++) {                                             \
        pa[f][0] = ar0[f * 8];                                                \
        pa[f][1] = ar8[f * 8];                                                \
        pa[f][2] = ar0[f * 8 + 4];                                            \
        pa[f][3] = ar8[f * 8 + 4];                                            \
    }                                                                         \
    _Pragma("unroll")                                                         \
    for (int f = 0; f < 4; f++)                                               \
        pb[f] = *(const float4*)&Bm[(size_t)(n0 + bN + f * 32) * DM_ + k0_ + bC4 * 4]; \
} while (0)

#define STS_CHUNK(s) do {                                                     \
    char* stg = smraw + (s) * STG;                                            \
    _Pragma("unroll")                                                         \
    for (int f = 0; f < 4; f++) {                                             \
        uint4 v;                                                              \
        v.x = to_tf32(pa[f][0]); v.y = to_tf32(pa[f][1]);                     \
        v.z = to_tf32(pa[f][2]); v.w = to_tf32(pa[f][3]);                     \
        *(uint4*)(stg + (size_t)(tid + f * 256) * 16) = v;                    \
    }                                                                         \
    uint32_t* bs = (uint32_t*)(stg + ASZ);                                    \
    _Pragma("unroll")                                                         \
    for (int f = 0; f < 4; f++) {                                             \
        uint32_t* d = bs + (bN + f * 32) * 36 + bC4 * 4;                      \
        d[0] = to_tf32(pb[f].x); d[1] = to_tf32(pb[f].y);                     \
        d[2] = to_tf32(pb[f].z); d[3] = to_tf32(pb[f].w);                     \
    }                                                                         \
} while (0)

#define MMA_CHUNK(s) do {                                                     \
    char* stg = smraw + (s) * STG;                                            \
    const uint32_t* bs = (const uint32_t*)(stg + ASZ);                        \
    _Pragma("unroll")                                                         \
    for (int kt = 0; kt < 4; kt++) {                                          \
        uint32_t af[4][4];                                                    \
        _Pragma("unroll")                                                     \
        for (int mt = 0; mt < 4; mt++) {                                      \
            uint4 v = *(const uint4*)(stg +                                   \
                (size_t)(((kt * 8) + (wm * 4 + mt)) * 32 + lane) * 16);       \
            af[mt][0] = v.x; af[mt][1] = v.y; af[mt][2] = v.z; af[mt][3] = v.w; \
        }                                                                     \
        uint32_t bf[4][2];                                                    \
        _Pragma("unroll")                                                     \
        for (int nt = 0; nt < 4; nt++) {                                      \
            const uint32_t* bp = bs +                                         \
                ((wn * 4 + nt) * 8 + (lane >> 2)) * 36 + kt * 8 + (lane & 3); \
            bf[nt][0] = bp[0];                                                \
            bf[nt][1] = bp[4];                                                \
        }                                                                     \
        _Pragma("unroll")                                                     \
        for (int mt = 0; mt < 4; mt++)                                        \
            _Pragma("unroll")                                                 \
            for (int nt = 0; nt < 4; nt++)                                    \
                mma_16n8k8(acc[mt][nt], af[mt], bf[nt]);                      \
    }                                                                         \
} while (0)

    LDG_CHUNK(0);
    STS_CHUNK(0);
    __syncthreads();

    for (int c = 0; c < 32; c++) {
        if (c < 31) LDG_CHUNK(c + 1);
        MMA_CHUNK(c & 1);
        if (c < 31) {
            STS_CHUNK((c + 1) & 1);
            __syncthreads();
        }
    }

#pragma unroll
    for (int mt = 0; mt < 4; mt++) {
#pragma unroll
        for (int nt = 0; nt < 4; nt++) {
            const int m = m0 + wm * 64 + mt * 16 + (lane >> 2);
            const int n = n0 + wn * 32 + nt * 8 + 2 * (lane & 3);
            float2 v01, v23;
            v01.x = acc[mt][nt][0] + bias[n];
            v01.y = acc[mt][nt][1] + bias[n + 1];
            v23.x = acc[mt][nt][2] + bias[n];
            v23.y = acc[mt][nt][3] + bias[n + 1];
            if (scatter) {
                const size_t base = (size_t)(n >> 6) * ((size_t)BSN_ * DH_) + (n & 63);
                *(float2*)&out[base + (size_t)m * DH_] = v01;
                *(float2*)&out[base + (size_t)(m + 8) * DH_] = v23;
            } else {
                *(float2*)&out[(size_t)m * DM_ + n] = v01;
                *(float2*)&out[(size_t)(m + 8) * DM_ + n] = v23;
            }
        }
    }
#undef LDG_CHUNK
#undef STS_CHUNK
#undef MMA_CHUNK
}

// ---------------------------------------------------------------------------
// Flash attention, tf32 mma.sync.
// CTA = 128 q-rows of one hb; 8 warps x 16 rows; K tiles of 64.
// SMEM (floats): Qp packed frags [0,8192), Ks [64][68] @8192,
//                Vs [64][72] @12544, Ps per-warp [16][68] @17152.
// ---------------------------------------------------------------------------
#define AT_KS 8192
#define AT_VS 12544
#define AT_PS 17152
#define ATTN_SMEM ((AT_PS + 8 * 16 * 68) * 4)   // 103424 bytes

__global__ __launch_bounds__(256, 2) void attn_mma(
    const float* __restrict__ Q, const float* __restrict__ K,
    const float* __restrict__ V, float* __restrict__ O)
{
    extern __shared__ __align__(16) float sm[];
    uint32_t* Qp = (uint32_t*)sm;
    uint32_t* Ks = (uint32_t*)(sm + AT_KS);
    uint32_t* Vs = (uint32_t*)(sm + AT_VS);

    const int tid = threadIdx.x, lane = tid & 31, wid = tid >> 5;
    const int g = lane >> 2, qd = lane & 3;
    uint32_t* Ps = (uint32_t*)(sm + AT_PS) + wid * (16 * 68);

    const int hb = blockIdx.y, q0 = blockIdx.x * 128;
    const float* Qg = Q + (size_t)hb * (S_ * DH_);
    const float* Kg = K + (size_t)hb * (S_ * DH_);
    const float* Vg = V + (size_t)hb * (S_ * DH_);

    // Q -> per-warp packed A-fragments (pre-scaled by 1/sqrt(64), tf32)
    {
        const int aR = wid * 16 + g;
        const float* r0 = Qg + (size_t)(q0 + aR) * DH_ + qd;
        const float* r8 = r0 + 8 * DH_;
#pragma unroll
        for (int kt = 0; kt < 8; kt++) {
            uint4 v;
            v.x = to_tf32(r0[kt * 8] * 0.125f);
            v.y = to_tf32(r8[kt * 8] * 0.125f);
            v.z = to_tf32(r0[kt * 8 + 4] * 0.125f);
            v.w = to_tf32(r8[kt * 8 + 4] * 0.125f);
            *(uint4*)(Qp + ((kt * 8 + wid) * 32 + lane) * 4) = v;
        }
    }

    float accO[8][4];
#pragma unroll
    for (int nt = 0; nt < 8; nt++)
#pragma unroll
        for (int i = 0; i < 4; i++) accO[nt][i] = 0.f;
    float m0 = -1e30f, m1 = -1e30f, l0 = 0.f, l1 = 0.f;

    for (int t = 0; t < 32; t++) {
        __syncthreads();   // prior tile's MMAs done reading Ks/Vs
        const int k0 = t * 64;
#pragma unroll
        for (int it = 0; it < 2; it++) {
            const int idx = tid + it * 256;
            const int row = idx >> 3, cc = (idx & 7) * 8;
            const float* kp = Kg + (size_t)(k0 + row) * DH_ + cc;
            float4 x = *(const float4*)kp;
            float4 y = *(const float4*)(kp + 4);
            uint4 u, w;
            u.x = to_tf32(x.x); u.y = to_tf32(x.y); u.z = to_tf32(x.z); u.w = to_tf32(x.w);
            w.x = to_tf32(y.x); w.y = to_tf32(y.y); w.z = to_tf32(y.z); w.w = to_tf32(y.w);
            *(uint4*)(Ks + row * 68 + cc) = u;
            *(uint4*)(Ks + row * 68 + cc + 4) = w;
            const float* vp = Vg + (size_t)(k0 + row) * DH_ + cc;
            x = *(const float4*)vp;
            y = *(const float4*)(vp + 4);
            u.x = to_tf32(x.x); u.y = to_tf32(x.y); u.z = to_tf32(x.z); u.w = to_tf32(x.w);
            w.x = to_tf32(y.x); w.y = to_tf32(y.y); w.z = to_tf32(y.z); w.w = to_tf32(y.w);
            *(uint4*)(Vs + row * 72 + cc) = u;
            *(uint4*)(Vs + row * 72 + cc + 4) = w;
        }
        __syncthreads();

        // S = (Q/8) K^T
        float s[8][4];
#pragma unroll
        for (int nt = 0; nt < 8; nt++)
#pragma unroll
            for (int i = 0; i < 4; i++) s[nt][i] = 0.f;
#pragma unroll
        for (int kt = 0; kt < 8; kt++) {
            uint4 av = *(const uint4*)(Qp + ((kt * 8 + wid) * 32 + lane) * 4);
            uint32_t a[4] = {av.x, av.y, av.z, av.w};
#pragma unroll
            for (int nt = 0; nt < 8; nt++) {
                const uint32_t* bp = Ks + (nt * 8 + g) * 68 + kt * 8 + qd;
                uint32_t b[2] = {bp[0], bp[4]};
                mma_16n8k8(s[nt], a, b);
            }
        }

        // online softmax (rows r=g, r+8 per thread; 4-lane row groups)
        float mn0 = m0, mn1 = m1;
#pragma unroll
        for (int nt = 0; nt < 8; nt++) {
            mn0 = fmaxf(mn0, fmaxf(s[nt][0], s[nt][1]));
            mn1 = fmaxf(mn1, fmaxf(s[nt][2], s[nt][3]));
        }
        mn0 = fmaxf(mn0, __shfl_xor_sync(0xffffffffu, mn0, 1));
        mn0 = fmaxf(mn0, __shfl_xor_sync(0xffffffffu, mn0, 2));
        mn1 = fmaxf(mn1, __shfl_xor_sync(0xffffffffu, mn1, 1));
        mn1 = fmaxf(mn1, __shfl_xor_sync(0xffffffffu, mn1, 2));
        const float c0 = __expf(m0 - mn0), c1 = __expf(m1 - mn1);
        m0 = mn0; m1 = mn1;
        float rs0 = 0.f, rs1 = 0.f;
#pragma unroll
        for (int nt = 0; nt < 8; nt++) {
            const float p0 = __expf(s[nt][0] - mn0);
            const float p1 = __expf(s[nt][1] - mn0);
            const float p2 = __expf(s[nt][2] - mn1);
            const float p3 = __expf(s[nt][3] - mn1);
            rs0 += p0 + p1;
            rs1 += p2 + p3;
            uint32_t* pr = Ps + g * 68 + nt * 8 + 2 * qd;
            pr[0] = to_tf32(p0);
            pr[1] = to_tf32(p1);
            pr[8 * 68] = to_tf32(p2);
            pr[8 * 68 + 1] = to_tf32(p3);
        }
        rs0 += __shfl_xor_sync(0xffffffffu, rs0, 1);
        rs0 += __shfl_xor_sync(0xffffffffu, rs0, 2);
        rs1 += __shfl_xor_sync(0xffffffffu, rs1, 1);
        rs1 += __shfl_xor_sync(0xffffffffu, rs1, 2);
        l0 = l0 * c0 + rs0;
        l1 = l1 * c1 + rs1;
#pragma unroll
        for (int nt = 0; nt < 8; nt++) {
            accO[nt][0] *= c0; accO[nt][1] *= c0;
            accO[nt][2] *= c1; accO[nt][3] *= c1;
        }
        __syncwarp();

        // O += P V   (A = P from warp-private smem, B = V)
#pragma unroll
        for (int kt = 0; kt < 8; kt++) {
            const uint32_t* ap = Ps + g * 68 + kt * 8 + qd;
            uint32_t a[4];
            a[0] = ap[0];
            a[1] = ap[8 * 68];
            a[2] = ap[4];
            a[3] = ap[8 * 68 + 4];
#pragma unroll
            for (int nt = 0; nt < 8; nt++) {
                const uint32_t* bp = Vs + (kt * 8 + qd) * 72 + nt * 8 + g;
                uint32_t b[2] = {bp[0], bp[4 * 72]};
                mma_16n8k8(accO[nt], a, b);
            }
        }
    }

    const float i0 = 1.f / l0, i1 = 1.f / l1;
    const size_t row0 = (size_t)hb * S_ + q0 + wid * 16 + g;
#pragma unroll
    for (int nt = 0; nt < 8; nt++) {
        float2 v0, v1;
        v0.x = accO[nt][0] * i0; v0.y = accO[nt][1] * i0;
        v1.x = accO[nt][2] * i1; v1.y = accO[nt][3] * i1;
        *(float2*)&O[row0 * DH_ + nt * 8 + 2 * qd] = v0;
        *(float2*)&O[(row0 + 8) * DH_ + nt * 8 + 2 * qd] = v1;
    }
}

// ---------------------------------------------------------------------------
extern "C" void kernel_launch(void* const* d_in, const int* in_sizes, int n_in,
                              void* d_out, int out_size)
{
    const float* query = (const float*)d_in[0];
    const float* key_  = (const float*)d_in[1];
    const float* value = (const float*)d_in[2];
    const float* Wq    = (const float*)d_in[3];
    const float* bq    = (const float*)d_in[4];
    const float* Wk    = (const float*)d_in[5];
    const float* bk    = (const float*)d_in[6];
    const float* Wv    = (const float*)d_in[7];
    const float* bv    = (const float*)d_in[8];
    const float* Wo    = (const float*)d_in[9];
    const float* bo    = (const float*)d_in[10];
    float* out = (float*)d_out;

    float *qb, *kb, *vb, *ab, *wq, *wk, *wv, *wo;
    cudaGetSymbolAddress((void**)&qb, g_q);
    cudaGetSymbolAddress((void**)&kb, g_k);
    cudaGetSymbolAddress((void**)&vb, g_v);
    cudaGetSymbolAddress((void**)&ab, g_att);
    cudaGetSymbolAddress((void**)&wq, g_wq);
    cudaGetSymbolAddress((void**)&wk, g_wk);
    cudaGetSymbolAddress((void**)&wv, g_wv);
    cudaGetSymbolAddress((void**)&wo, g_wo);

    cudaFuncSetAttribute(gemm_mma, cudaFuncAttributeMaxDynamicSharedMemorySize, GEMM_SMEM);
    cudaFuncSetAttribute(attn_mma, cudaFuncAttributeMaxDynamicSharedMemorySize, ATTN_SMEM);

    repack_w<<<dim3(16, 16), 256>>>(Wq, wq);
    repack_w<<<dim3(16, 16), 256>>>(Wk, wk);
    repack_w<<<dim3(16, 16), 256>>>(Wv, wv);
    transpose_wo<<<dim3(16, 16), 256>>>(Wo, wo);

    const dim3 gGemm(DM_ / 128, BSN_ / 128);   // (8, 32)
    gemm_mma<<<gGemm, 256, GEMM_SMEM>>>(query, wq, bq, qb, 1);
    gemm_mma<<<gGemm, 256, GEMM_SMEM>>>(key_,  wk, bk, kb, 1);
    gemm_mma<<<gGemm, 256, GEMM_SMEM>>>(value, wv, bv, vb, 1);

    const dim3 gAttn(S_ / 128, HB_);           // (16, 32)
    attn_mma<<<gAttn, 256, ATTN_SMEM>>>(qb, kb, vb, ab);

    gemm_mma<<<gGemm, 256, GEMM_SMEM>>>(ab, wo, bo, out, 0);
}

// round 6
// speedup vs baseline: 3.2766x; 1.2900x over previous
#include <cuda_runtime.h>
#include <cstdint>
#include <math.h>

#define B_   2
#define S_   2048
#define DM_  1024
#define H_   16
#define DH_  64
#define BSN_ (B_ * S_)     // 4096 rows
#define HB_  (H_ * B_)     // 32 (head,batch) pairs
#define PLANE_ (HB_ * S_ * DH_)

// Scratch. g_qkv = [q|k|v] planes, each [H][B][S][DH]. g_att flat == Wo GEMM input.
__device__ float g_qkv[3 * PLANE_];
__device__ float g_att[PLANE_];
__device__ float g_w[4 * DM_ * DM_];   // repacked [n][k] K-major: Wq,Wk,Wv,Wo^T

// ---------------------------------------------------------------------------
// helpers
// ---------------------------------------------------------------------------
__device__ __forceinline__ uint32_t smem_u32(const void* p) {
    uint32_t a;
    asm("{ .reg .u64 t; cvta.to.shared.u64 t, %1; cvt.u32.u64 %0, t; }"
        : "=r"(a) : "l"(p));
    return a;
}
__device__ __forceinline__ uint32_t to_tf32(float x) {
    uint32_t r;
    asm("cvt.rna.tf32.f32 %0, %1;" : "=r"(r) : "f"(x));
    return r;
}
__device__ __forceinline__ void mma_16n8k8(float* c, const uint32_t* a, const uint32_t* b) {
    asm volatile(
        "mma.sync.aligned.m16n8k8.row.col.f32.tf32.tf32.f32 "
        "{%0,%1,%2,%3}, {%4,%5,%6,%7}, {%8,%9}, {%0,%1,%2,%3};\n"
        : "+f"(c[0]), "+f"(c[1]), "+f"(c[2]), "+f"(c[3])
        : "r"(a[0]), "r"(a[1]), "r"(a[2]), "r"(a[3]), "r"(b[0]), "r"(b[1]));
}
#define CP16(dst, src) \
    asm volatile("{ .reg .u64 gp; cvta.to.global.u64 gp, %1; " \
                 "cp.async.ca.shared.global [%0], [gp], 16; }" \
                 :: "r"(dst), "l"(src) : "memory")
#define CP_COMMIT() asm volatile("cp.async.commit_group;" ::: "memory")
#define CP_WAIT1()  asm volatile("cp.async.wait_group 1;" ::: "memory")
#define CP_WAIT2()  asm volatile("cp.async.wait_group 2;" ::: "memory")

// ---------------------------------------------------------------------------
// Repack all weights (tf32-rounded): z<3: W[H][DM][DH] -> Wall[z][n][k];
// z==3: Wo[k][n] -> Wall[3][n][k]
// ---------------------------------------------------------------------------
__global__ __launch_bounds__(256) void repack_all(
    const float* __restrict__ Wq, const float* __restrict__ Wk,
    const float* __restrict__ Wv, const float* __restrict__ Wo,
    float* __restrict__ Wall)
{
    __shared__ float t[64][65];
    const int z = blockIdx.z, tid = threadIdx.x;
    float v[16];
    if (z < 3) {
        const float* W = z == 0 ? Wq : (z == 1 ? Wk : Wv);
        const int h = blockIdx.x, d0 = blockIdx.y * 64;
        const float* src = W + (size_t)h * DM_ * DH_;
#pragma unroll
        for (int j = 0; j < 16; j++) {
            const int i = tid + j * 256;
            v[j] = src[(size_t)(d0 + (i >> 6)) * DH_ + (i & 63)];
        }
#pragma unroll
        for (int j = 0; j < 16; j++) {
            const int i = tid + j * 256;
            t[i >> 6][i & 63] = v[j];
        }
        __syncthreads();
        float* dst = Wall + (size_t)z * DM_ * DM_;
#pragma unroll
        for (int j = 0; j < 16; j++) {
            const int i = tid + j * 256;
            const int jj = i >> 6, d = i & 63;
            dst[(size_t)(h * 64 + jj) * DM_ + d0 + d] = __uint_as_float(to_tf32(t[d][jj]));
        }
    } else {
        const int k0 = blockIdx.x * 64, n0 = blockIdx.y * 64;
#pragma unroll
        for (int j = 0; j < 16; j++) {
            const int i = tid + j * 256;
            v[j] = Wo[(size_t)(k0 + (i >> 6)) * DM_ + n0 + (i & 63)];
        }
#pragma unroll
        for (int j = 0; j < 16; j++) {
            const int i = tid + j * 256;
            t[i >> 6][i & 63] = v[j];
        }
        __syncthreads();
        float* dst = Wall + (size_t)3 * DM_ * DM_;
#pragma unroll
        for (int j = 0; j < 16; j++) {
            const int i = tid + j * 256;
            const int n = i >> 6, k = i & 63;
            dst[(size_t)(n0 + n) * DM_ + k0 + k] = __uint_as_float(to_tf32(t[k][n]));
        }
    }
}

// ---------------------------------------------------------------------------
// GEMM core: C[4096,1024] = A @ Bm^T (+bias). 3-stage cp.async pipeline.
// SMEM/stage: As[128][36] fp32 then Bs[128][36] tf32-bits. Stage=36864 B.
// A frags cvt-on-lds (rna, idempotent); B frags raw (pre-rounded).
// scatter=1: tf32-rounded write to [H,B,S,64] layout; scatter=0: plain fp32.
// ---------------------------------------------------------------------------
#define GPAD 36
#define STG_F (2 * 128 * GPAD)          // floats per stage = 9216
#define GEMM_SMEM (3 * STG_F * 4)       // 110592 bytes

__device__ __forceinline__ void gemm_body(
    const float* __restrict__ A, const float* __restrict__ Bm,
    const float* __restrict__ bias, float* __restrict__ out,
    const int scatter, float* sm, const uint32_t sb)
{
    const int tid = threadIdx.x, lane = tid & 31, wid = tid >> 5;
    const int g = lane >> 2, qd = lane & 3;
    const int wm = wid & 1, wn = wid >> 1;
    const int m0 = blockIdx.y * 128, n0 = blockIdx.x * 128;

    float acc[4][4][4];
#pragma unroll
    for (int i = 0; i < 4; i++)
#pragma unroll
        for (int j = 0; j < 4; j++)
#pragma unroll
            for (int k = 0; k < 4; k++) acc[i][j][k] = 0.f;

#define GLOAD(c, s) do {                                                      \
    const int k0_ = (c) * 32;                                                 \
    const uint32_t abase = sb + (s) * (STG_F * 4);                            \
    const uint32_t bbase = abase + 128 * GPAD * 4;                            \
    _Pragma("unroll")                                                         \
    for (int j = 0; j < 4; j++) {                                             \
        const int idx = tid + j * 256;                                        \
        const int row = idx >> 3, ch = (idx & 7) * 4;                         \
        CP16(abase + (row * GPAD + ch) * 4,                                   \
             A + (size_t)(m0 + row) * DM_ + k0_ + ch);                        \
        CP16(bbase + (row * GPAD + ch) * 4,                                   \
             Bm + (size_t)(n0 + row) * DM_ + k0_ + ch);                       \
    }                                                                         \
    CP_COMMIT();                                                              \
} while (0)

    GLOAD(0, 0); GLOAD(1, 1); GLOAD(2, 2);

    for (int c = 0; c < 32; c++) {
        const int s = c - (c / 3) * 3;
        CP_WAIT2();
        __syncthreads();
        const float* as = sm + s * STG_F;
        const uint32_t* bs = (const uint32_t*)(as + 128 * GPAD);
#pragma unroll
        for (int kt = 0; kt < 4; kt++) {
            uint32_t af[4][4];
#pragma unroll
            for (int mt = 0; mt < 4; mt++) {
                const float* p = as + ((wm * 4 + mt) * 16 + g) * GPAD + kt * 8 + qd;
                af[mt][0] = to_tf32(p[0]);
                af[mt][1] = to_tf32(p[8 * GPAD]);
                af[mt][2] = to_tf32(p[4]);
                af[mt][3] = to_tf32(p[8 * GPAD + 4]);
            }
            uint32_t bf[4][2];
#pragma unroll
            for (int nt = 0; nt < 4; nt++) {
                const uint32_t* p = bs + ((wn * 4 + nt) * 8 + g) * GPAD + kt * 8 + qd;
                bf[nt][0] = p[0];
                bf[nt][1] = p[4];
            }
#pragma unroll
            for (int mt = 0; mt < 4; mt++)
#pragma unroll
                for (int nt = 0; nt < 4; nt++)
                    mma_16n8k8(acc[mt][nt], af[mt], bf[nt]);
        }
        __syncthreads();
        if (c < 29) GLOAD(c + 3, s); else CP_COMMIT();
    }
#undef GLOAD

#pragma unroll
    for (int mt = 0; mt < 4; mt++) {
#pragma unroll
        for (int nt = 0; nt < 4; nt++) {
            const int m = m0 + wm * 64 + mt * 16 + g;
            const int n = n0 + wn * 32 + nt * 8 + 2 * qd;
            float2 v01, v23;
            v01.x = acc[mt][nt][0] + bias[n];
            v01.y = acc[mt][nt][1] + bias[n + 1];
            v23.x = acc[mt][nt][2] + bias[n];
            v23.y = acc[mt][nt][3] + bias[n + 1];
            if (scatter) {
                v01.x = __uint_as_float(to_tf32(v01.x));
                v01.y = __uint_as_float(to_tf32(v01.y));
                v23.x = __uint_as_float(to_tf32(v23.x));
                v23.y = __uint_as_float(to_tf32(v23.y));
                const size_t base = (size_t)(n >> 6) * ((size_t)BSN_ * DH_) + (n & 63);
                *(float2*)&out[base + (size_t)m * DH_] = v01;
                *(float2*)&out[base + (size_t)(m + 8) * DH_] = v23;
            } else {
                *(float2*)&out[(size_t)m * DM_ + n] = v01;
                *(float2*)&out[(size_t)(m + 8) * DM_ + n] = v23;
            }
        }
    }
}

__global__ __launch_bounds__(256, 2) void gemm_qkv(
    const float* __restrict__ Aq, const float* __restrict__ Ak,
    const float* __restrict__ Av, const float* __restrict__ Wall,
    const float* __restrict__ b0, const float* __restrict__ b1,
    const float* __restrict__ b2, float* __restrict__ outqkv)
{
    extern __shared__ __align__(16) float sm[];
    const int z = blockIdx.z;
    const float* A = z == 0 ? Aq : (z == 1 ? Ak : Av);
    const float* bias = z == 0 ? b0 : (z == 1 ? b1 : b2);
    gemm_body(A, Wall + (size_t)z * DM_ * DM_, bias,
              outqkv + (size_t)z * PLANE_, 1, sm, smem_u32(sm));
}

__global__ __launch_bounds__(256, 2) void gemm_o(
    const float* __restrict__ A, const float* __restrict__ Bm,
    const float* __restrict__ bias, float* __restrict__ out)
{
    extern __shared__ __align__(16) float sm[];
    gemm_body(A, Bm, bias, out, 0, sm, smem_u32(sm));
}

// ---------------------------------------------------------------------------
// Flash attention: Q in registers (pre-rounded, x0.125 exact), K/V 2-stage
// cp.async double buffer (raw, pre-rounded tf32), P per-warp smem.
// SMEM (floats): stage s @ s*8960: K[64][68] then V[64][72]; Ps @ 17920.
// ---------------------------------------------------------------------------
#define AT_STGF 8960
#define AT_PS   17920
#define ATTN_SMEM ((AT_PS + 8 * 16 * 68) * 4)   // 106496 bytes

__global__ __launch_bounds__(256, 2) void attn_mma(
    const float* __restrict__ Q, const float* __restrict__ K,
    const float* __restrict__ V, float* __restrict__ O)
{
    extern __shared__ __align__(16) float sm[];
    const uint32_t sb = smem_u32(sm);
    const int tid = threadIdx.x, lane = tid & 31, wid = tid >> 5;
    const int g = lane >> 2, qd = lane & 3;
    uint32_t* Ps = (uint32_t*)sm + AT_PS + wid * (16 * 68);

    const int hb = blockIdx.y, q0 = blockIdx.x * 128;
    const float* Qg = Q + (size_t)hb * (S_ * DH_);
    const float* Kg = K + (size_t)hb * (S_ * DH_);
    const float* Vg = V + (size_t)hb * (S_ * DH_);

    // Q fragments in registers (values already tf32; *0.125 is exact)
    uint32_t qf[8][4];
    {
        const float* r0 = Qg + (size_t)(q0 + wid * 16 + g) * DH_ + qd;
        const float* r8 = r0 + 8 * DH_;
#pragma unroll
        for (int kt = 0; kt < 8; kt++) {
            qf[kt][0] = __float_as_uint(r0[kt * 8] * 0.125f);
            qf[kt][1] = __float_as_uint(r8[kt * 8] * 0.125f);
            qf[kt][2] = __float_as_uint(r0[kt * 8 + 4] * 0.125f);
            qf[kt][3] = __float_as_uint(r8[kt * 8 + 4] * 0.125f);
        }
    }

#define KVLOAD(t, st) do {                                                    \
    const int k0_ = (t) * 64;                                                 \
    const uint32_t kb = sb + (st) * (AT_STGF * 4);                            \
    const uint32_t vb = kb + 64 * 68 * 4;                                     \
    _Pragma("unroll")                                                         \
    for (int j = 0; j < 4; j++) {                                             \
        const int idx = tid + j * 256;                                        \
        const int row = idx >> 4, ch = (idx & 15) * 4;                        \
        CP16(kb + (row * 68 + ch) * 4, Kg + (size_t)(k0_ + row) * DH_ + ch);  \
        CP16(vb + (row * 72 + ch) * 4, Vg + (size_t)(k0_ + row) * DH_ + ch);  \
    }                                                                         \
    CP_COMMIT();                                                              \
} while (0)

    float accO[8][4];
#pragma unroll
    for (int nt = 0; nt < 8; nt++)
#pragma unroll
        for (int i = 0; i < 4; i++) accO[nt][i] = 0.f;
    float m0 = -1e30f, m1 = -1e30f, l0 = 0.f, l1 = 0.f;

    KVLOAD(0, 0);
    KVLOAD(1, 1);

    for (int t = 0; t < 32; t++) {
        const int st = t & 1;
        CP_WAIT1();
        __syncthreads();
        const uint32_t* Ks = (const uint32_t*)sm + st * AT_STGF;
        const uint32_t* Vs = Ks + 64 * 68;

        // S = (Q/8) K^T
        float s[8][4];
#pragma unroll
        for (int nt = 0; nt < 8; nt++)
#pragma unroll
            for (int i = 0; i < 4; i++) s[nt][i] = 0.f;
#pragma unroll
        for (int kt = 0; kt < 8; kt++) {
#pragma unroll
            for (int nt = 0; nt < 8; nt++) {
                const uint32_t* bp = Ks + (nt * 8 + g) * 68 + kt * 8 + qd;
                uint32_t b[2] = {bp[0], bp[4]};
                mma_16n8k8(s[nt], qf[kt], b);
            }
        }

        // online softmax (rows g, g+8; 4-lane row groups)
        float mn0 = m0, mn1 = m1;
#pragma unroll
        for (int nt = 0; nt < 8; nt++) {
            mn0 = fmaxf(mn0, fmaxf(s[nt][0], s[nt][1]));
            mn1 = fmaxf(mn1, fmaxf(s[nt][2], s[nt][3]));
        }
        mn0 = fmaxf(mn0, __shfl_xor_sync(0xffffffffu, mn0, 1));
        mn0 = fmaxf(mn0, __shfl_xor_sync(0xffffffffu, mn0, 2));
        mn1 = fmaxf(mn1, __shfl_xor_sync(0xffffffffu, mn1, 1));
        mn1 = fmaxf(mn1, __shfl_xor_sync(0xffffffffu, mn1, 2));
        const float c0 = __expf(m0 - mn0), c1 = __expf(m1 - mn1);
        m0 = mn0; m1 = mn1;
        float rs0 = 0.f, rs1 = 0.f;
#pragma unroll
        for (int nt = 0; nt < 8; nt++) {
            const float p0 = __expf(s[nt][0] - mn0);
            const float p1 = __expf(s[nt][1] - mn0);
            const float p2 = __expf(s[nt][2] - mn1);
            const float p3 = __expf(s[nt][3] - mn1);
            rs0 += p0 + p1;
            rs1 += p2 + p3;
            uint32_t* pr = Ps + g * 68 + nt * 8 + 2 * qd;
            pr[0] = to_tf32(p0);
            pr[1] = to_tf32(p1);
            pr[8 * 68] = to_tf32(p2);
            pr[8 * 68 + 1] = to_tf32(p3);
        }
        rs0 += __shfl_xor_sync(0xffffffffu, rs0, 1);
        rs0 += __shfl_xor_sync(0xffffffffu, rs0, 2);
        rs1 += __shfl_xor_sync(0xffffffffu, rs1, 1);
        rs1 += __shfl_xor_sync(0xffffffffu, rs1, 2);
        l0 = l0 * c0 + rs0;
        l1 = l1 * c1 + rs1;
#pragma unroll
        for (int nt = 0; nt < 8; nt++) {
            accO[nt][0] *= c0; accO[nt][1] *= c0;
            accO[nt][2] *= c1; accO[nt][3] *= c1;
        }
        __syncwarp();

        // O += P V
#pragma unroll
        for (int kt = 0; kt < 8; kt++) {
            const uint32_t* ap = Ps + g * 68 + kt * 8 + qd;
            uint32_t a[4];
            a[0] = ap[0];
            a[1] = ap[8 * 68];
            a[2] = ap[4];
            a[3] = ap[8 * 68 + 4];
#pragma unroll
            for (int nt = 0; nt < 8; nt++) {
                const uint32_t* bp = Vs + (kt * 8 + qd) * 72 + nt * 8 + g;
                uint32_t b[2] = {bp[0], bp[4 * 72]};
                mma_16n8k8(accO[nt], a, b);
            }
        }
        __syncthreads();
        if (t < 30) KVLOAD(t + 2, st); else CP_COMMIT();
    }
#undef KVLOAD

    const float i0 = 1.f / l0, i1 = 1.f / l1;
    const size_t row0 = (size_t)hb * S_ + q0 + wid * 16 + g;
#pragma unroll
    for (int nt = 0; nt < 8; nt++) {
        float2 v0, v1;
        v0.x = accO[nt][0] * i0; v0.y = accO[nt][1] * i0;
        v1.x = accO[nt][2] * i1; v1.y = accO[nt][3] * i1;
        *(float2*)&O[row0 * DH_ + nt * 8 + 2 * qd] = v0;
        *(float2*)&O[(row0 + 8) * DH_ + nt * 8 + 2 * qd] = v1;
    }
}

// ---------------------------------------------------------------------------
extern "C" void kernel_launch(void* const* d_in, const int* in_sizes, int n_in,
                              void* d_out, int out_size)
{
    const float* query = (const float*)d_in[0];
    const float* key_  = (const float*)d_in[1];
    const float* value = (const float*)d_in[2];
    const float* Wq    = (const float*)d_in[3];
    const float* bq    = (const float*)d_in[4];
    const float* Wk    = (const float*)d_in[5];
    const float* bk    = (const float*)d_in[6];
    const float* Wv    = (const float*)d_in[7];
    const float* bv    = (const float*)d_in[8];
    const float* Wo    = (const float*)d_in[9];
    const float* bo    = (const float*)d_in[10];
    float* out = (float*)d_out;

    float *qkv, *ab, *wall;
    cudaGetSymbolAddress((void**)&qkv, g_qkv);
    cudaGetSymbolAddress((void**)&ab, g_att);
    cudaGetSymbolAddress((void**)&wall, g_w);

    cudaFuncSetAttribute(gemm_qkv, cudaFuncAttributeMaxDynamicSharedMemorySize, GEMM_SMEM);
    cudaFuncSetAttribute(gemm_o, cudaFuncAttributeMaxDynamicSharedMemorySize, GEMM_SMEM);
    cudaFuncSetAttribute(attn_mma, cudaFuncAttributeMaxDynamicSharedMemorySize, ATTN_SMEM);

    repack_all<<<dim3(16, 16, 4), 256>>>(Wq, Wk, Wv, Wo, wall);

    gemm_qkv<<<dim3(8, 32, 3), 256, GEMM_SMEM>>>(query, key_, value, wall,
                                                 bq, bk, bv, qkv);

    attn_mma<<<dim3(S_ / 128, HB_), 256, ATTN_SMEM>>>(qkv, qkv + PLANE_,
                                                      qkv + 2 * PLANE_, ab);

    gemm_o<<<dim3(8, 32), 256, GEMM_SMEM>>>(ab, wall + (size_t)3 * DM_ * DM_, bo, out);
}